// round 13
// baseline (speedup 1.0000x reference)
#include <cuda_runtime.h>
#include <math.h>

// ---------------------------------------------------------------------------
// TensorizedSpectralConv: B=32, H=W=128, C=128, modes 32x17, deg 2, rank 64
// Round 12: tcgen05 blocked by harness PTX target (compute_103, not 103a).
// Incremental: mix double-buffered Ksm (1 barrier/chunk, no prefetch),
// fwdW depth-2 LDG pipeline, invW unroll-2. Base = 344us config.
// ---------------------------------------------------------------------------

#define BATCH 32
#define NHH   128
#define NWW   128
#define CI    128
#define CO    128
#define WM    17
#define HM    32
#define DEG   2
#define RANK  64
#define NHW   (HM*WM)   // 544

typedef unsigned long long u64;

__device__ u64    g_X1[BATCH*WM*NHH*CI];     // 71.3 MB  [b][w][y][c] (re,im)
__device__ float4 g_S0[HM*CO*CI];            //  8.4 MB  (d0.re,d0.im,d1.re,d1.im)
__device__ float4 g_S1[WM*CO*CI];            //  4.5 MB
__device__ float2 g_Xf[NHW*BATCH*CI];        // 17.8 MB  [h][w][b][c]
__device__ float2 g_Yf[NHW*BATCH*CO];        // 17.8 MB  [h][w][b][i]
__device__ float2 g_Z [BATCH*NHH*WM*CO];     // 71.3 MB  [b][y][w][i]

__device__ __forceinline__ u64 pk2(float x, float y) {
    u64 r; asm("mov.b64 %0,{%1,%2};" : "=l"(r) : "f"(x), "f"(y)); return r;
}
__device__ __forceinline__ void up2(u64 v, float& x, float& y) {
    asm("mov.b64 {%0,%1},%2;" : "=f"(x), "=f"(y) : "l"(v));
}
__device__ __forceinline__ u64 f2fma(u64 a, u64 b, u64 c) {
    u64 d; asm("fma.rn.f32x2 %0,%1,%2,%3;" : "=l"(d) : "l"(a), "l"(b), "l"(c)); return d;
}
__device__ __forceinline__ u64 f2add(u64 a, u64 b) {
    u64 d; asm("add.rn.f32x2 %0,%1,%2;" : "=l"(d) : "l"(a), "l"(b)); return d;
}

__device__ __forceinline__ float2 cfma(float2 a, float2 b, float2 acc) {
    acc.x = fmaf(a.x, b.x, acc.x);
    acc.x = fmaf(-a.y, b.y, acc.x);
    acc.y = fmaf(a.x, b.y, acc.y);
    acc.y = fmaf(a.y, b.x, acc.y);
    return acc;
}

// ---------------------------------------------------------------------------
// S build (both axes in one launch): block per (axis, mode, d, i-chunk-of-16).
// ---------------------------------------------------------------------------
__global__ void __launch_bounds__(256) s_kernel(const float2* __restrict__ ko0,
                                                const float2* __restrict__ ki0,
                                                const float2* __restrict__ ko1,
                                                const float2* __restrict__ ki1) {
    int which = (blockIdx.x >= HM * DEG);
    int hd = which ? (blockIdx.x - HM * DEG) : blockIdx.x;
    const float2* ko = which ? ko1 : ko0;
    const float2* ki = which ? ki1 : ki0;
    float4* S = which ? g_S1 : g_S0;
    int h  = hd >> 1;
    int d  = hd & 1;
    int i0 = blockIdx.y * 16;
    __shared__ float2 kis[128][33];
    __shared__ float2 kos[16][33];
    int tid = threadIdx.x;
    int j = tid & 127, ih = tid >> 7;

    float2 acc[8];
#pragma unroll
    for (int ii = 0; ii < 8; ii++) acc[ii] = make_float2(0.f, 0.f);

    for (int r0 = 0; r0 < RANK; r0 += 32) {
        __syncthreads();
        for (int t = tid; t < 128 * 32; t += 256) {
            int jj = t >> 5, r = t & 31;
            kis[jj][r] = ki[((h * CI + jj) * DEG + d) * RANK + r0 + r];
        }
        for (int t = tid; t < 16 * 32; t += 256) {
            int ii = t >> 5, r = t & 31;
            kos[ii][r] = ko[((h * CO + i0 + ii) * DEG + d) * RANK + r0 + r];
        }
        __syncthreads();
        for (int r = 0; r < 32; r++) {
            float2 bj = kis[j][r];
#pragma unroll
            for (int ii = 0; ii < 8; ii++)
                acc[ii] = cfma(kos[ih * 8 + ii][r], bj, acc[ii]);
        }
    }
#pragma unroll
    for (int ii = 0; ii < 8; ii++) {
        int i = i0 + ih * 8 + ii;
        ((float2*)&S[(size_t)(h * CO + i) * CI + j])[d] = acc[ii];
    }
}

// ---------------------------------------------------------------------------
// Forward W DFT (real input, 17 modes). Even/odd split + pair fold, f32x2,
// depth-2 LDG pipeline (loads for u+2 issued before FMAs of u).
// ---------------------------------------------------------------------------
__global__ void __launch_bounds__(256) fwdW_kernel(const float* __restrict__ X) {
    __shared__ u64 tw2[17][33];   // (cos(2pi w u/128), -sin(...)), u in [0,32]
    int tid = threadIdx.x;
    for (int t = tid; t < 17 * 33; t += 256) {
        int w = t / 33, u = t % 33;
        float s, c;
        sincospif((float)(w * u) / 64.0f, &s, &c);
        tw2[w][u] = pk2(c, -s);
    }
    __syncthreads();

    int c = tid & 127, ys = tid >> 7;
    int b = blockIdx.x >> 6;
    int y = ((blockIdx.x & 63) << 1) | ys;
    const float* base = X + ((size_t)(b * NHH + y) * NWW) * CI + c;

    float v0  = base[0],       v32 = base[32 * CI];
    float v64 = base[64 * CI], v96 = base[96 * CI];
    float pE0  = v0 + v64,  pO0  = v0 - v64;
    float pE32 = v32 + v96, pO32 = v32 - v96;

    u64 accE[9], accO[8];
#pragma unroll
    for (int e = 0; e < 9; e++)
        accE[e] = pk2(pE0 + ((e & 1) ? -pE32 : pE32), 0.f);
#pragma unroll
    for (int o = 0; o < 8; o++)
        accO[o] = pk2(pO0, (o & 1) ? pO32 : -pO32);

    // pipeline registers: cur = values for u, nxt = values for u+1
    float a0 = base[1 * CI],  b0 = base[65 * CI];
    float c0 = base[63 * CI], d0 = base[127 * CI];
    float a1 = base[2 * CI],  b1 = base[66 * CI];
    float c1 = base[62 * CI], d1 = base[126 * CI];

    for (int u = 1; u < 32; u++) {
        // issue loads for u+2 (clamped; duplicate load at the tail is unused)
        int un = (u + 2 <= 31) ? (u + 2) : 31;
        float a2 = base[un * CI];
        float b2 = base[(un + 64) * CI];
        float c2 = base[(64 - un) * CI];
        float d2 = base[(128 - un) * CI];

        float pEu = a0 + b0, pOu = a0 - b0;
        float pEv = c0 + d0, pOv = c0 - d0;
        u64 sdE = pk2(pEu + pEv, pEu - pEv);
        u64 dsO = pk2(pOu - pOv, pOu + pOv);
#pragma unroll
        for (int e = 0; e < 9; e++)
            accE[e] = f2fma(sdE, tw2[2 * e][u], accE[e]);
#pragma unroll
        for (int o = 0; o < 8; o++)
            accO[o] = f2fma(dsO, tw2[2 * o + 1][u], accO[o]);

        a0 = a1; b0 = b1; c0 = c1; d0 = d1;
        a1 = a2; b1 = b2; c1 = c2; d1 = d2;
    }

    u64* dst = g_X1 + ((size_t)b * WM * NHH + y) * CI + c;
#pragma unroll
    for (int w = 0; w < WM; w++)
        dst[(size_t)w * NHH * CI] = (w & 1) ? accO[w >> 1] : accE[w >> 1];
}

// ---------------------------------------------------------------------------
// Forward H DFT (32 kept modes), even/odd split over y+64 (mode parity = h&1)
// + pair fold over 64-y, f32x2. Block per (b,w); 1024 threads = 32 h x 32 lanes.
// ---------------------------------------------------------------------------
__global__ void __launch_bounds__(1024) fwdH_kernel() {
    __shared__ u64 stg[4][16][128];   // 64KB: [sE, dEm, dO, sOm]
    __shared__ u64 twcc[128], twss[128];
    int tid = threadIdx.x;
    if (tid < 128) {
        float s, c;
        sincospif((float)tid / 64.0f, &s, &c);
        twcc[tid] = pk2(c, c);
        twss[tid] = pk2(s, s);
    }
    int b = blockIdx.x / WM, w = blockIdx.x % WM;
    int lane = tid & 31, h = tid >> 5;
    int m = (h < 16) ? h : (96 + h);
    int p = h & 1;
    float sg = ((h >> 1) & 1) ? -1.f : 1.f;
    const u64* src = g_X1 + ((size_t)b * WM + w) * NHH * CI;

    u64 acc[4];
#pragma unroll
    for (int q = 0; q < 4; q++) {
        int c = lane + 32 * q;
        float r0, i0, r32, i32, r64, i64, r96, i96;
        up2(src[c], r0, i0);
        up2(src[32 * CI + c], r32, i32);
        up2(src[64 * CI + c], r64, i64);
        up2(src[96 * CI + c], r96, i96);
        if (p == 0) {
            acc[q] = pk2(fmaf(sg, r32 + r96, r0 + r64),
                         fmaf(sg, i32 + i96, i0 + i64));
        } else {
            acc[q] = pk2(fmaf(sg, i32 - i96, r0 - r64),
                         fmaf(-sg, r32 - r96, i0 - i64));
        }
    }

    const u64* sPtr = p ? &stg[2][0][0] : &stg[0][0][0];
    const u64* mPtr = p ? &stg[3][0][0] : &stg[1][0][0];

    for (int chunk = 0; chunk < 2; chunk++) {
        int ylo = 1 + 16 * chunk;
        int cnt = chunk ? 15 : 16;
        __syncthreads();
        for (int t = tid; t < cnt * 128; t += 1024) {
            int yy = t >> 7, cc = t & 127;
            int yp = ylo + yy;
            float ar, ai, br, bi, cr, ci2, dr, di;
            up2(src[(size_t)yp * CI + cc], ar, ai);
            up2(src[(size_t)(yp + 64) * CI + cc], br, bi);
            up2(src[(size_t)(64 - yp) * CI + cc], cr, ci2);
            up2(src[(size_t)(128 - yp) * CI + cc], dr, di);
            float pEyr = ar + br, pEyi = ai + bi;
            float pOyr = ar - br, pOyi = ai - bi;
            float pEvr = cr + dr, pEvi = ci2 + di;
            float pOvr = cr - dr, pOvi = ci2 - di;
            stg[0][yy][cc] = pk2(pEyr + pEvr, pEyi + pEvi);
            stg[1][yy][cc] = pk2(pEyi - pEvi, -(pEyr - pEvr));
            stg[2][yy][cc] = pk2(pOyr - pOvr, pOyi - pOvi);
            stg[3][yy][cc] = pk2(pOyi + pOvi, -(pOyr + pOvr));
        }
        __syncthreads();
#pragma unroll 4
        for (int yy = 0; yy < cnt; yy++) {
            int idx = (m * (ylo + yy)) & 127;
            u64 cc = twcc[idx], ss = twss[idx];
#pragma unroll
            for (int q = 0; q < 4; q++) {
                int c = lane + 32 * q;
                acc[q] = f2fma(sPtr[yy * 128 + c], cc, acc[q]);
                acc[q] = f2fma(mPtr[yy * 128 + c], ss, acc[q]);
            }
        }
    }
    u64* dst = (u64*)g_Xf + ((size_t)(h * WM + w) * BATCH + b) * CI;
#pragma unroll
    for (int q = 0; q < 4; q++) dst[lane + 32 * q] = acc[q];
}

// ---------------------------------------------------------------------------
// Mode mix: f32x2 P/Q accumulators, K on the fly, DOUBLE-BUFFERED Ksm with
// one barrier per chunk (no prefetch — the only delta vs the 87.5us version).
// 512 threads: thread (i = tid&127, bq = tid>>7) owns 8 b's. 2 blocks/SM.
// ---------------------------------------------------------------------------
__global__ void __launch_bounds__(512, 2) mix_kernel() {
    __shared__ ulonglong2 xsm[32][64];    // 32KB: x[b][j] pairs (j even/odd)
    __shared__ float4 Ksm[2][4][129];     // 16.5KB double-buffered
    int tid = threadIdx.x;
    int hw = blockIdx.x;
    int h = hw / WM, w = hw % WM;
    int i = tid & 127, bq = tid >> 7;
    const float4* A  = g_S0 + (size_t)h * CO * CI;
    const float4* Bm = g_S1 + (size_t)w * CO * CI;
    const u64* Xb = (const u64*)g_Xf + (size_t)hw * BATCH * CI;
    const float SCALE = 1.0f / 16384.0f;

    // stage all x once; chunk 0's barrier covers visibility
    u64* xflat = (u64*)xsm;
    for (int t = tid; t < 32 * 128; t += 512)
        xflat[t] = Xb[(t >> 7) * CI + (t & 127)];

    int kjj2 = tid & 3, kii = tid >> 2;

    u64 accP[8], accQ[8];
#pragma unroll
    for (int bb = 0; bb < 8; bb++) { accP[bb] = 0; accQ[bb] = 0; }

    for (int chunk = 0; chunk < 16; chunk++) {
        int buf = chunk & 1;
        {
            int e = kii * CI + chunk * 8 + 2 * kjj2;
            float4 pa0 = A[e], pa1 = A[e + 1];
            float4 pb0 = Bm[e], pb1 = Bm[e + 1];
            float kr0 = pa0.x * pb0.x - pa0.y * pb0.y + pa0.z * pb0.z - pa0.w * pb0.w;
            float ki0 = pa0.x * pb0.y + pa0.y * pb0.x + pa0.z * pb0.w + pa0.w * pb0.z;
            float kr1 = pa1.x * pb1.x - pa1.y * pb1.y + pa1.z * pb1.z - pa1.w * pb1.w;
            float ki1 = pa1.x * pb1.y + pa1.y * pb1.x + pa1.z * pb1.w + pa1.w * pb1.z;
            Ksm[buf][kjj2][kii] = make_float4(kr0 * SCALE, ki0 * SCALE,
                                              kr1 * SCALE, ki1 * SCALE);
        }
        __syncthreads();   // single barrier: buf written by all, prev-buf reads done
#pragma unroll
        for (int jj2 = 0; jj2 < 4; jj2++) {
            float4 kk = Ksm[buf][jj2][i];
            u64 kc0 = pk2(kk.x, kk.x), ks0 = pk2(kk.y, kk.y);
            u64 kc1 = pk2(kk.z, kk.z), ks1 = pk2(kk.w, kk.w);
            int jidx = chunk * 4 + jj2;
#pragma unroll
            for (int bb = 0; bb < 8; bb++) {
                ulonglong2 xx = xsm[bq * 8 + bb][jidx];
                accP[bb] = f2fma(xx.x, kc0, accP[bb]);
                accQ[bb] = f2fma(xx.x, ks0, accQ[bb]);
                accP[bb] = f2fma(xx.y, kc1, accP[bb]);
                accQ[bb] = f2fma(xx.y, ks1, accQ[bb]);
            }
        }
    }
    float2* dst = g_Yf + (size_t)hw * BATCH * CO;
#pragma unroll
    for (int bb = 0; bb < 8; bb++) {
        float pr, pi, qr, qi;
        up2(accP[bb], pr, pi);
        up2(accQ[bb], qr, qi);
        dst[(bq * 8 + bb) * CO + i] = make_float2(pr - qi, pi + qr);
    }
}

// ---------------------------------------------------------------------------
// Inverse H with even/odd output split: Z(y)=accE+accO, Z(y+64)=accE-accO.
// ---------------------------------------------------------------------------
__global__ void __launch_bounds__(512) invH_kernel() {
    __shared__ u64 ys[32][128];
    __shared__ u64 twcc[128];
    __shared__ u64 twss[128];
    int tid = threadIdx.x;
    if (tid < 128) {
        float s, c;
        sincospif((float)tid / 64.0f, &s, &c);
        twcc[tid] = pk2(c, c);
        twss[tid] = pk2(s, s);
    }
    int hw = blockIdx.x;
    int b = hw / WM, w = hw % WM;
    int i = tid & 127, ysub = tid >> 7;
    int yb = blockIdx.y * 32 + ysub * 8;   // y in [0,64)

    const u64* Ysrc = (const u64*)g_Yf;
    for (int t = tid; t < 32 * 128; t += 512) {
        int h = t >> 7, ii = t & 127;
        ys[h][ii] = Ysrc[((size_t)(h * WM + w) * BATCH + b) * CO + ii];
    }
    __syncthreads();

    u64 accE[8], accO[8];
    {
        u64 v0 = ys[0][i];
#pragma unroll
        for (int k = 0; k < 8; k++) { accE[k] = v0; accO[k] = 0; }
    }
    {   // m = -16 (h=16, even)
        u64 v = ys[16][i];
        float vr, vi; up2(v, vr, vi);
        u64 vs = pk2(vi, -vr);
        int idx = (16 * yb) & 127;
#pragma unroll
        for (int k = 0; k < 8; k++) {
            accE[k] = f2fma(v,  twcc[idx], accE[k]);
            accE[k] = f2fma(vs, twss[idx], accE[k]);
            idx = (idx + 16) & 127;
        }
    }
#pragma unroll 2
    for (int m = 2; m < 16; m += 2) {
        u64 y1 = ys[m][i], y2 = ys[32 - m][i];
        float ar, ai, br, bi;
        up2(y1, ar, ai); up2(y2, br, bi);
        u64 s  = pk2(ar + br, ai + bi);
        u64 dp = pk2(-(ai - bi), ar - br);
        int idx = (m * yb) & 127;
#pragma unroll
        for (int k = 0; k < 8; k++) {
            accE[k] = f2fma(s,  twcc[idx], accE[k]);
            accE[k] = f2fma(dp, twss[idx], accE[k]);
            idx = (idx + m) & 127;
        }
    }
#pragma unroll 2
    for (int m = 1; m < 16; m += 2) {
        u64 y1 = ys[m][i], y2 = ys[32 - m][i];
        float ar, ai, br, bi;
        up2(y1, ar, ai); up2(y2, br, bi);
        u64 s  = pk2(ar + br, ai + bi);
        u64 dp = pk2(-(ai - bi), ar - br);
        int idx = (m * yb) & 127;
#pragma unroll
        for (int k = 0; k < 8; k++) {
            accO[k] = f2fma(s,  twcc[idx], accO[k]);
            accO[k] = f2fma(dp, twss[idx], accO[k]);
            idx = (idx + m) & 127;
        }
    }
    u64* Zd = (u64*)g_Z;
    const u64 NEG1 = pk2(-1.f, -1.f);
#pragma unroll
    for (int k = 0; k < 8; k++) {
        int y = yb + k;
        Zd[((size_t)(b * NHH + y) * WM + w) * CO + i] = f2add(accE[k], accO[k]);
        Zd[((size_t)(b * NHH + y + 64) * WM + w) * CO + i] = f2fma(accO[k], NEG1, accE[k]);
    }
}

// ---------------------------------------------------------------------------
// Inverse W (hermitian, real output), even/odd + pair symmetry, f32x2,
// split accumulator chains, unroll-2 over x. 256 threads = 2 y rows.
// ---------------------------------------------------------------------------
__global__ void __launch_bounds__(256) invW_kernel(float* __restrict__ out) {
    __shared__ u64 tw2[17][33];
    int tid = threadIdx.x;
    for (int t = tid; t < 17 * 33; t += 256) {
        int w = t / 33, x = t % 33;
        float s, c;
        sincospif((float)(w * x) / 64.0f, &s, &c);
        tw2[w][x] = pk2(c, -s);
    }
    __syncthreads();

    int c = tid & 127, ysp = tid >> 7;
    int b = blockIdx.x >> 6;
    int y = ((blockIdx.x & 63) << 1) | ysp;
    const float2* zrow = g_Z + (size_t)(b * NHH + y) * WM * CO;

    u64 zw[WM];
#pragma unroll
    for (int w = 0; w < WM; w++) {
        float2 v = zrow[w * CO + c];
        float cw = (w == 0) ? 1.0f : 2.0f;
        zw[w] = pk2(v.x * cw, v.y * cw);
    }

    float* orow = out + (size_t)(b * NHH + y) * NWW * CO + c;
#pragma unroll 2
    for (int x = 0; x <= 32; x++) {
        u64 aE0 = 0, aE1 = 0, aO0 = 0, aO1 = 0;
#pragma unroll
        for (int e = 0; e < 5; e++)
            aE0 = f2fma(zw[2 * e], tw2[2 * e][x], aE0);
#pragma unroll
        for (int e = 5; e < 9; e++)
            aE1 = f2fma(zw[2 * e], tw2[2 * e][x], aE1);
#pragma unroll
        for (int o = 0; o < 4; o++)
            aO0 = f2fma(zw[2 * o + 1], tw2[2 * o + 1][x], aO0);
#pragma unroll
        for (int o = 4; o < 8; o++)
            aO1 = f2fma(zw[2 * o + 1], tw2[2 * o + 1][x], aO1);
        u64 aE = f2add(aE0, aE1);
        u64 aO = f2add(aO0, aO1);
        float eR, eI, oR, oI;
        up2(aE, eR, eI);
        up2(aO, oR, oI);
        float a0 = eR + oR, b0 = eI + oI;
        float a1 = eR - oR, b1 = eI - oI;
        if (x == 0) {
            orow[0]            = a0 + b0;
            orow[64 * CO]      = a1 + b1;
        } else if (x == 32) {
            orow[32 * CO]      = a0 + b0;
            orow[96 * CO]      = a1 + b1;
        } else {
            orow[(size_t)x * CO]          = a0 + b0;
            orow[(size_t)(128 - x) * CO]  = a0 - b0;
            orow[(size_t)(x + 64) * CO]   = a1 + b1;
            orow[(size_t)(64 - x) * CO]   = a1 - b1;
        }
    }
}

// ---------------------------------------------------------------------------
extern "C" void kernel_launch(void* const* d_in, const int* in_sizes, int n_in,
                              void* d_out, int out_size) {
    const float*  X   = (const float*) d_in[0];
    const float2* ko0 = (const float2*)d_in[1];
    const float2* ki0 = (const float2*)d_in[2];
    const float2* ko1 = (const float2*)d_in[3];
    const float2* ki1 = (const float2*)d_in[4];
    float* out = (float*)d_out;

    s_kernel<<<dim3(HM * DEG + WM * DEG, 8), 256>>>(ko0, ki0, ko1, ki1);
    fwdW_kernel<<<BATCH * 64, 256>>>(X);
    fwdH_kernel<<<BATCH * WM, 1024>>>();
    mix_kernel<<<NHW, 512>>>();
    invH_kernel<<<dim3(BATCH * WM, 2), 512>>>();
    invW_kernel<<<BATCH * 64, 256>>>(out);
}

// round 14
// speedup vs baseline: 1.0221x; 1.0221x over previous
#include <cuda_runtime.h>
#include <math.h>

// ---------------------------------------------------------------------------
// TensorizedSpectralConv: B=32, H=W=128, C=128, modes 32x17, deg 2, rank 64
// Round 13: revert to 344us config + fuse invH+invW (g_Z eliminated, 143MB
// DRAM traffic saved). Phase1/phase2 reuse the proven inner loops verbatim.
// ---------------------------------------------------------------------------

#define BATCH 32
#define NHH   128
#define NWW   128
#define CI    128
#define CO    128
#define WM    17
#define HM    32
#define DEG   2
#define RANK  64
#define NHW   (HM*WM)   // 544

typedef unsigned long long u64;

__device__ u64    g_X1[BATCH*WM*NHH*CI];     // 71.3 MB  [b][w][y][c] (re,im)
__device__ float4 g_S0[HM*CO*CI];            //  8.4 MB
__device__ float4 g_S1[WM*CO*CI];            //  4.5 MB
__device__ float2 g_Xf[NHW*BATCH*CI];        // 17.8 MB  [h][w][b][c]
__device__ float2 g_Yf[NHW*BATCH*CO];        // 17.8 MB  [h][w][b][i]

__device__ __forceinline__ u64 pk2(float x, float y) {
    u64 r; asm("mov.b64 %0,{%1,%2};" : "=l"(r) : "f"(x), "f"(y)); return r;
}
__device__ __forceinline__ void up2(u64 v, float& x, float& y) {
    asm("mov.b64 {%0,%1},%2;" : "=f"(x), "=f"(y) : "l"(v));
}
__device__ __forceinline__ u64 f2fma(u64 a, u64 b, u64 c) {
    u64 d; asm("fma.rn.f32x2 %0,%1,%2,%3;" : "=l"(d) : "l"(a), "l"(b), "l"(c)); return d;
}
__device__ __forceinline__ u64 f2add(u64 a, u64 b) {
    u64 d; asm("add.rn.f32x2 %0,%1,%2;" : "=l"(d) : "l"(a), "l"(b)); return d;
}

__device__ __forceinline__ float2 cfma(float2 a, float2 b, float2 acc) {
    acc.x = fmaf(a.x, b.x, acc.x);
    acc.x = fmaf(-a.y, b.y, acc.x);
    acc.y = fmaf(a.x, b.y, acc.y);
    acc.y = fmaf(a.y, b.x, acc.y);
    return acc;
}

// ---------------------------------------------------------------------------
// S build (both axes in one launch): block per (axis, mode, d, i-chunk-of-16).
// ---------------------------------------------------------------------------
__global__ void __launch_bounds__(256) s_kernel(const float2* __restrict__ ko0,
                                                const float2* __restrict__ ki0,
                                                const float2* __restrict__ ko1,
                                                const float2* __restrict__ ki1) {
    int which = (blockIdx.x >= HM * DEG);
    int hd = which ? (blockIdx.x - HM * DEG) : blockIdx.x;
    const float2* ko = which ? ko1 : ko0;
    const float2* ki = which ? ki1 : ki0;
    float4* S = which ? g_S1 : g_S0;
    int h  = hd >> 1;
    int d  = hd & 1;
    int i0 = blockIdx.y * 16;
    __shared__ float2 kis[128][33];
    __shared__ float2 kos[16][33];
    int tid = threadIdx.x;
    int j = tid & 127, ih = tid >> 7;

    float2 acc[8];
#pragma unroll
    for (int ii = 0; ii < 8; ii++) acc[ii] = make_float2(0.f, 0.f);

    for (int r0 = 0; r0 < RANK; r0 += 32) {
        __syncthreads();
        for (int t = tid; t < 128 * 32; t += 256) {
            int jj = t >> 5, r = t & 31;
            kis[jj][r] = ki[((h * CI + jj) * DEG + d) * RANK + r0 + r];
        }
        for (int t = tid; t < 16 * 32; t += 256) {
            int ii = t >> 5, r = t & 31;
            kos[ii][r] = ko[((h * CO + i0 + ii) * DEG + d) * RANK + r0 + r];
        }
        __syncthreads();
        for (int r = 0; r < 32; r++) {
            float2 bj = kis[j][r];
#pragma unroll
            for (int ii = 0; ii < 8; ii++)
                acc[ii] = cfma(kos[ih * 8 + ii][r], bj, acc[ii]);
        }
    }
#pragma unroll
    for (int ii = 0; ii < 8; ii++) {
        int i = i0 + ih * 8 + ii;
        ((float2*)&S[(size_t)(h * CO + i) * CI + j])[d] = acc[ii];
    }
}

// ---------------------------------------------------------------------------
// Forward W DFT (real input, 17 modes). Even/odd split + pair fold, f32x2.
// ---------------------------------------------------------------------------
__global__ void __launch_bounds__(256) fwdW_kernel(const float* __restrict__ X) {
    __shared__ u64 tw2[17][33];   // (cos(2pi w u/128), -sin(...)), u in [0,32]
    int tid = threadIdx.x;
    for (int t = tid; t < 17 * 33; t += 256) {
        int w = t / 33, u = t % 33;
        float s, c;
        sincospif((float)(w * u) / 64.0f, &s, &c);
        tw2[w][u] = pk2(c, -s);
    }
    __syncthreads();

    int c = tid & 127, ys = tid >> 7;
    int b = blockIdx.x >> 6;
    int y = ((blockIdx.x & 63) << 1) | ys;
    const float* base = X + ((size_t)(b * NHH + y) * NWW) * CI + c;

    float v0  = base[0],       v32 = base[32 * CI];
    float v64 = base[64 * CI], v96 = base[96 * CI];
    float pE0  = v0 + v64,  pO0  = v0 - v64;
    float pE32 = v32 + v96, pO32 = v32 - v96;

    u64 accE[9], accO[8];
#pragma unroll
    for (int e = 0; e < 9; e++)
        accE[e] = pk2(pE0 + ((e & 1) ? -pE32 : pE32), 0.f);
#pragma unroll
    for (int o = 0; o < 8; o++)
        accO[o] = pk2(pO0, (o & 1) ? pO32 : -pO32);

    for (int u = 1; u < 32; u++) {
        float va = base[u * CI];
        float vb = base[(u + 64) * CI];
        float vc = base[(64 - u) * CI];
        float vd = base[(128 - u) * CI];
        float pEu = va + vb, pOu = va - vb;
        float pEv = vc + vd, pOv = vc - vd;
        u64 sdE = pk2(pEu + pEv, pEu - pEv);
        u64 dsO = pk2(pOu - pOv, pOu + pOv);
#pragma unroll
        for (int e = 0; e < 9; e++)
            accE[e] = f2fma(sdE, tw2[2 * e][u], accE[e]);
#pragma unroll
        for (int o = 0; o < 8; o++)
            accO[o] = f2fma(dsO, tw2[2 * o + 1][u], accO[o]);
    }

    u64* dst = g_X1 + ((size_t)b * WM * NHH + y) * CI + c;
#pragma unroll
    for (int w = 0; w < WM; w++)
        dst[(size_t)w * NHH * CI] = (w & 1) ? accO[w >> 1] : accE[w >> 1];
}

// ---------------------------------------------------------------------------
// Forward H DFT (32 kept modes), even/odd + pair fold, f32x2.
// ---------------------------------------------------------------------------
__global__ void __launch_bounds__(1024) fwdH_kernel() {
    __shared__ u64 stg[4][16][128];
    __shared__ u64 twcc[128], twss[128];
    int tid = threadIdx.x;
    if (tid < 128) {
        float s, c;
        sincospif((float)tid / 64.0f, &s, &c);
        twcc[tid] = pk2(c, c);
        twss[tid] = pk2(s, s);
    }
    int b = blockIdx.x / WM, w = blockIdx.x % WM;
    int lane = tid & 31, h = tid >> 5;
    int m = (h < 16) ? h : (96 + h);
    int p = h & 1;
    float sg = ((h >> 1) & 1) ? -1.f : 1.f;
    const u64* src = g_X1 + ((size_t)b * WM + w) * NHH * CI;

    u64 acc[4];
#pragma unroll
    for (int q = 0; q < 4; q++) {
        int c = lane + 32 * q;
        float r0, i0, r32, i32, r64, i64, r96, i96;
        up2(src[c], r0, i0);
        up2(src[32 * CI + c], r32, i32);
        up2(src[64 * CI + c], r64, i64);
        up2(src[96 * CI + c], r96, i96);
        if (p == 0) {
            acc[q] = pk2(fmaf(sg, r32 + r96, r0 + r64),
                         fmaf(sg, i32 + i96, i0 + i64));
        } else {
            acc[q] = pk2(fmaf(sg, i32 - i96, r0 - r64),
                         fmaf(-sg, r32 - r96, i0 - i64));
        }
    }

    const u64* sPtr = p ? &stg[2][0][0] : &stg[0][0][0];
    const u64* mPtr = p ? &stg[3][0][0] : &stg[1][0][0];

    for (int chunk = 0; chunk < 2; chunk++) {
        int ylo = 1 + 16 * chunk;
        int cnt = chunk ? 15 : 16;
        __syncthreads();
        for (int t = tid; t < cnt * 128; t += 1024) {
            int yy = t >> 7, cc = t & 127;
            int yp = ylo + yy;
            float ar, ai, br, bi, cr, ci2, dr, di;
            up2(src[(size_t)yp * CI + cc], ar, ai);
            up2(src[(size_t)(yp + 64) * CI + cc], br, bi);
            up2(src[(size_t)(64 - yp) * CI + cc], cr, ci2);
            up2(src[(size_t)(128 - yp) * CI + cc], dr, di);
            float pEyr = ar + br, pEyi = ai + bi;
            float pOyr = ar - br, pOyi = ai - bi;
            float pEvr = cr + dr, pEvi = ci2 + di;
            float pOvr = cr - dr, pOvi = ci2 - di;
            stg[0][yy][cc] = pk2(pEyr + pEvr, pEyi + pEvi);
            stg[1][yy][cc] = pk2(pEyi - pEvi, -(pEyr - pEvr));
            stg[2][yy][cc] = pk2(pOyr - pOvr, pOyi - pOvi);
            stg[3][yy][cc] = pk2(pOyi + pOvi, -(pOyr + pOvr));
        }
        __syncthreads();
#pragma unroll 4
        for (int yy = 0; yy < cnt; yy++) {
            int idx = (m * (ylo + yy)) & 127;
            u64 cc = twcc[idx], ss = twss[idx];
#pragma unroll
            for (int q = 0; q < 4; q++) {
                int c = lane + 32 * q;
                acc[q] = f2fma(sPtr[yy * 128 + c], cc, acc[q]);
                acc[q] = f2fma(mPtr[yy * 128 + c], ss, acc[q]);
            }
        }
    }
    u64* dst = (u64*)g_Xf + ((size_t)(h * WM + w) * BATCH + b) * CI;
#pragma unroll
    for (int q = 0; q < 4; q++) dst[lane + 32 * q] = acc[q];
}

// ---------------------------------------------------------------------------
// Mode mix (measured-best 87.5us version, unchanged).
// ---------------------------------------------------------------------------
__global__ void __launch_bounds__(512, 2) mix_kernel() {
    __shared__ ulonglong2 xsm[32][64];
    __shared__ float4 Ksm[4][129];
    int tid = threadIdx.x;
    int hw = blockIdx.x;
    int h = hw / WM, w = hw % WM;
    int i = tid & 127, bq = tid >> 7;
    const float4* A  = g_S0 + (size_t)h * CO * CI;
    const float4* Bm = g_S1 + (size_t)w * CO * CI;
    const u64* Xb = (const u64*)g_Xf + (size_t)hw * BATCH * CI;
    const float SCALE = 1.0f / 16384.0f;

    u64* xflat = (u64*)xsm;
    for (int t = tid; t < 32 * 128; t += 512)
        xflat[t] = Xb[(t >> 7) * CI + (t & 127)];

    int kjj2 = tid & 3, kii = tid >> 2;

    u64 accP[8], accQ[8];
#pragma unroll
    for (int bb = 0; bb < 8; bb++) { accP[bb] = 0; accQ[bb] = 0; }

    for (int chunk = 0; chunk < 16; chunk++) {
        __syncthreads();
        {
            int e = kii * CI + chunk * 8 + 2 * kjj2;
            float4 pa0 = A[e], pa1 = A[e + 1];
            float4 pb0 = Bm[e], pb1 = Bm[e + 1];
            float kr0 = pa0.x * pb0.x - pa0.y * pb0.y + pa0.z * pb0.z - pa0.w * pb0.w;
            float ki0 = pa0.x * pb0.y + pa0.y * pb0.x + pa0.z * pb0.w + pa0.w * pb0.z;
            float kr1 = pa1.x * pb1.x - pa1.y * pb1.y + pa1.z * pb1.z - pa1.w * pb1.w;
            float ki1 = pa1.x * pb1.y + pa1.y * pb1.x + pa1.z * pb1.w + pa1.w * pb1.z;
            Ksm[kjj2][kii] = make_float4(kr0 * SCALE, ki0 * SCALE, kr1 * SCALE, ki1 * SCALE);
        }
        __syncthreads();
#pragma unroll
        for (int jj2 = 0; jj2 < 4; jj2++) {
            float4 kk = Ksm[jj2][i];
            u64 kc0 = pk2(kk.x, kk.x), ks0 = pk2(kk.y, kk.y);
            u64 kc1 = pk2(kk.z, kk.z), ks1 = pk2(kk.w, kk.w);
            int jidx = chunk * 4 + jj2;
#pragma unroll
            for (int bb = 0; bb < 8; bb++) {
                ulonglong2 xx = xsm[bq * 8 + bb][jidx];
                accP[bb] = f2fma(xx.x, kc0, accP[bb]);
                accQ[bb] = f2fma(xx.x, ks0, accQ[bb]);
                accP[bb] = f2fma(xx.y, kc1, accP[bb]);
                accQ[bb] = f2fma(xx.y, ks1, accQ[bb]);
            }
        }
    }
    float2* dst = g_Yf + (size_t)hw * BATCH * CO;
#pragma unroll
    for (int bb = 0; bb < 8; bb++) {
        float pr, pi, qr, qi;
        up2(accP[bb], pr, pi);
        up2(accQ[bb], qr, qi);
        dst[(bq * 8 + bb) * CO + i] = make_float2(pr - qi, pi + qr);
    }
}

// ---------------------------------------------------------------------------
// Fused inverse (invH + invW), g_Z eliminated.
// Block = (b, i-quarter): Yf slice [32h][17w][32i] resident in smem (139KB).
// Per 8-y chunk: phase1 (thread = (w, i), 17 warps) = invH inner producing
// even/odd partial rows ZE/ZO[8y][17w][32i]; phase2 (512 threads = (i, 8y x
// 2 halves)) = invW inner on zw = ZE +- ZO, storing to out. x2 hermitian
// weight folded into tw2. Dynamic smem 215.4KB, 1 block/SM, 128 blocks.
// ---------------------------------------------------------------------------
#define FU_YF   0
#define FU_ZE   139264
#define FU_ZO   174080
#define FU_TWC  208896
#define FU_TWS  209920
#define FU_TW2  210944
#define FU_SMEM (210944 + 17*33*8)   // 215432

__global__ void __launch_bounds__(544, 1) invHW_kernel(float* __restrict__ out) {
    extern __shared__ char sm[];
    u64* YF   = (u64*)(sm + FU_YF);    // [h][w][ii] = h*544 + w*32 + ii
    u64* ZE   = (u64*)(sm + FU_ZE);    // [y8][w][ii]
    u64* ZO   = (u64*)(sm + FU_ZO);
    u64* twcc = (u64*)(sm + FU_TWC);
    u64* twss = (u64*)(sm + FU_TWS);
    u64* tw2  = (u64*)(sm + FU_TW2);   // [w][x] = w*33+x, cw folded
    int tid = threadIdx.x;
    int b = blockIdx.x >> 2, i0 = (blockIdx.x & 3) * 32;

    if (tid < 128) {
        float s, c;
        sincospif((float)tid / 64.0f, &s, &c);
        twcc[tid] = pk2(c, c);
        twss[tid] = pk2(s, s);
    }
    for (int t = tid; t < 17 * 33; t += 544) {
        int w = t / 33, x = t % 33;
        float s, c;
        sincospif((float)(w * x) / 64.0f, &s, &c);
        float cw = (w == 0) ? 1.0f : 2.0f;
        tw2[t] = pk2(cw * c, -cw * s);
    }
    // load Yf slice: (h, w, i0+ii)
    const u64* Ysrc = (const u64*)g_Yf;
    for (int t = tid; t < 32 * 544; t += 544) {
        int h = t / 544, rem = t % 544;
        int w = rem >> 5, ii = rem & 31;
        YF[t] = Ysrc[((size_t)(h * WM + w) * BATCH + b) * CO + i0 + ii];
    }
    __syncthreads();

    int pw = tid >> 5, plane = tid & 31;          // phase-1 mapping (17 warps)
    const u64* yfw = YF + pw * 32 + plane;        // index by h: yfw[h*544]
    int ii2 = tid & 31, slot = tid >> 5;          // phase-2 mapping
    int y8 = slot & 7, half = slot >> 3;
    const u64 NEG1 = pk2(-1.f, -1.f);

    for (int ch = 0; ch < 8; ch++) {
        int y0 = ch * 8;
        // ---- phase 1: invH inner (exact round-10 structure) ----
        u64 accE[8], accO[8];
        {
            u64 v0 = yfw[0];
#pragma unroll
            for (int k = 0; k < 8; k++) { accE[k] = v0; accO[k] = 0; }
        }
        {   // m = -16 (h=16, even)
            u64 v = yfw[16 * 544];
            float vr, vi; up2(v, vr, vi);
            u64 vs = pk2(vi, -vr);
            int idx = (16 * y0) & 127;
#pragma unroll
            for (int k = 0; k < 8; k++) {
                accE[k] = f2fma(v,  twcc[idx], accE[k]);
                accE[k] = f2fma(vs, twss[idx], accE[k]);
                idx = (idx + 16) & 127;
            }
        }
#pragma unroll 2
        for (int m = 2; m < 16; m += 2) {
            u64 y1 = yfw[m * 544], y2 = yfw[(32 - m) * 544];
            float ar, ai, br, bi;
            up2(y1, ar, ai); up2(y2, br, bi);
            u64 s  = pk2(ar + br, ai + bi);
            u64 dp = pk2(-(ai - bi), ar - br);
            int idx = (m * y0) & 127;
#pragma unroll
            for (int k = 0; k < 8; k++) {
                accE[k] = f2fma(s,  twcc[idx], accE[k]);
                accE[k] = f2fma(dp, twss[idx], accE[k]);
                idx = (idx + m) & 127;
            }
        }
#pragma unroll 2
        for (int m = 1; m < 16; m += 2) {
            u64 y1 = yfw[m * 544], y2 = yfw[(32 - m) * 544];
            float ar, ai, br, bi;
            up2(y1, ar, ai); up2(y2, br, bi);
            u64 s  = pk2(ar + br, ai + bi);
            u64 dp = pk2(-(ai - bi), ar - br);
            int idx = (m * y0) & 127;
#pragma unroll
            for (int k = 0; k < 8; k++) {
                accO[k] = f2fma(s,  twcc[idx], accO[k]);
                accO[k] = f2fma(dp, twss[idx], accO[k]);
                idx = (idx + m) & 127;
            }
        }
#pragma unroll
        for (int k = 0; k < 8; k++) {
            ZE[(k * 17 + pw) * 32 + plane] = accE[k];
            ZO[(k * 17 + pw) * 32 + plane] = accO[k];
        }
        __syncthreads();

        // ---- phase 2: invW inner (exact round-10 structure) ----
        if (tid < 512) {
            int y = y0 + y8 + half * 64;
            u64 zw[17];
            if (half == 0) {
#pragma unroll
                for (int w = 0; w < WM; w++)
                    zw[w] = f2add(ZE[(y8 * 17 + w) * 32 + ii2],
                                  ZO[(y8 * 17 + w) * 32 + ii2]);
            } else {
#pragma unroll
                for (int w = 0; w < WM; w++)
                    zw[w] = f2fma(ZO[(y8 * 17 + w) * 32 + ii2], NEG1,
                                  ZE[(y8 * 17 + w) * 32 + ii2]);
            }
            float* orow = out + ((size_t)(b * NHH + y) * NWW) * CO + i0 + ii2;
            for (int x = 0; x <= 32; x++) {
                u64 aE0 = 0, aE1 = 0, aO0 = 0, aO1 = 0;
#pragma unroll
                for (int e = 0; e < 5; e++)
                    aE0 = f2fma(zw[2 * e], tw2[(2 * e) * 33 + x], aE0);
#pragma unroll
                for (int e = 5; e < 9; e++)
                    aE1 = f2fma(zw[2 * e], tw2[(2 * e) * 33 + x], aE1);
#pragma unroll
                for (int o = 0; o < 4; o++)
                    aO0 = f2fma(zw[2 * o + 1], tw2[(2 * o + 1) * 33 + x], aO0);
#pragma unroll
                for (int o = 4; o < 8; o++)
                    aO1 = f2fma(zw[2 * o + 1], tw2[(2 * o + 1) * 33 + x], aO1);
                u64 aE = f2add(aE0, aE1);
                u64 aO = f2add(aO0, aO1);
                float eR, eI, oR, oI;
                up2(aE, eR, eI);
                up2(aO, oR, oI);
                float a0 = eR + oR, b0 = eI + oI;   // acc(x)
                float a1 = eR - oR, b1 = eI - oI;   // acc(x+64)
                if (x == 0) {
                    orow[0]       = a0 + b0;
                    orow[64 * CO] = a1 + b1;
                } else if (x == 32) {
                    orow[32 * CO] = a0 + b0;
                    orow[96 * CO] = a1 + b1;
                } else {
                    orow[(size_t)x * CO]         = a0 + b0;
                    orow[(size_t)(128 - x) * CO] = a0 - b0;
                    orow[(size_t)(x + 64) * CO]  = a1 + b1;
                    orow[(size_t)(64 - x) * CO]  = a1 - b1;
                }
            }
        }
        __syncthreads();   // ZE/ZO reusable next chunk
    }
}

// ---------------------------------------------------------------------------
extern "C" void kernel_launch(void* const* d_in, const int* in_sizes, int n_in,
                              void* d_out, int out_size) {
    const float*  X   = (const float*) d_in[0];
    const float2* ko0 = (const float2*)d_in[1];
    const float2* ki0 = (const float2*)d_in[2];
    const float2* ko1 = (const float2*)d_in[3];
    const float2* ki1 = (const float2*)d_in[4];
    float* out = (float*)d_out;

    cudaFuncSetAttribute(invHW_kernel,
                         cudaFuncAttributeMaxDynamicSharedMemorySize, FU_SMEM);

    s_kernel<<<dim3(HM * DEG + WM * DEG, 8), 256>>>(ko0, ki0, ko1, ki1);
    fwdW_kernel<<<BATCH * 64, 256>>>(X);
    fwdH_kernel<<<BATCH * WM, 1024>>>();
    mix_kernel<<<NHW, 512>>>();
    invHW_kernel<<<BATCH * 4, 544, FU_SMEM>>>(out);
}

// round 15
// speedup vs baseline: 1.0672x; 1.0441x over previous
#include <cuda_runtime.h>
#include <math.h>

// ---------------------------------------------------------------------------
// TensorizedSpectralConv: B=32, H=W=128, C=128, modes 32x17, deg 2, rank 64
// Round 14: revert invHW fusion (regressed). 344us config + s_kernel merged
// into the fwdW launch (independent work, hidden behind fwdW).
// ---------------------------------------------------------------------------

#define BATCH 32
#define NHH   128
#define NWW   128
#define CI    128
#define CO    128
#define WM    17
#define HM    32
#define DEG   2
#define RANK  64
#define NHW   (HM*WM)   // 544

typedef unsigned long long u64;

__device__ u64    g_X1[BATCH*WM*NHH*CI];     // 71.3 MB  [b][w][y][c] (re,im)
__device__ float4 g_S0[HM*CO*CI];            //  8.4 MB
__device__ float4 g_S1[WM*CO*CI];            //  4.5 MB
__device__ float2 g_Xf[NHW*BATCH*CI];        // 17.8 MB  [h][w][b][c]
__device__ float2 g_Yf[NHW*BATCH*CO];        // 17.8 MB  [h][w][b][i]
__device__ float2 g_Z [BATCH*NHH*WM*CO];     // 71.3 MB  [b][y][w][i]

__device__ __forceinline__ u64 pk2(float x, float y) {
    u64 r; asm("mov.b64 %0,{%1,%2};" : "=l"(r) : "f"(x), "f"(y)); return r;
}
__device__ __forceinline__ void up2(u64 v, float& x, float& y) {
    asm("mov.b64 {%0,%1},%2;" : "=f"(x), "=f"(y) : "l"(v));
}
__device__ __forceinline__ u64 f2fma(u64 a, u64 b, u64 c) {
    u64 d; asm("fma.rn.f32x2 %0,%1,%2,%3;" : "=l"(d) : "l"(a), "l"(b), "l"(c)); return d;
}
__device__ __forceinline__ u64 f2add(u64 a, u64 b) {
    u64 d; asm("add.rn.f32x2 %0,%1,%2;" : "=l"(d) : "l"(a), "l"(b)); return d;
}

__device__ __forceinline__ float2 cfma(float2 a, float2 b, float2 acc) {
    acc.x = fmaf(a.x, b.x, acc.x);
    acc.x = fmaf(-a.y, b.y, acc.x);
    acc.y = fmaf(a.x, b.y, acc.y);
    acc.y = fmaf(a.y, b.x, acc.y);
    return acc;
}

// ---------------------------------------------------------------------------
// Merged launch: blocks [0, 2048) = fwdW; blocks [2048, 2832) = S build.
// Both bodies verbatim from the 344us config; independent data.
// ---------------------------------------------------------------------------
#define SFW_FWDW_BLOCKS (BATCH * 64)            // 2048
#define SFW_S_BLOCKS    ((HM + WM) * DEG * 8)   // 784
#define SFW_TOTAL       (SFW_FWDW_BLOCKS + SFW_S_BLOCKS)

__global__ void __launch_bounds__(256) s_fwdW_kernel(
    const float* __restrict__ X,
    const float2* __restrict__ ko0, const float2* __restrict__ ki0,
    const float2* __restrict__ ko1, const float2* __restrict__ ki1) {
    __shared__ u64 tw2[17][33];          // fwdW branch (4.5KB)
    __shared__ float2 kis[128][33];      // s branch (33KB)
    __shared__ float2 kos[16][33];       // s branch (4.2KB)
    int tid = threadIdx.x;

    if (blockIdx.x < SFW_FWDW_BLOCKS) {
        // ------------------- fwdW: even/odd split + pair fold -------------
        for (int t = tid; t < 17 * 33; t += 256) {
            int w = t / 33, u = t % 33;
            float s, c;
            sincospif((float)(w * u) / 64.0f, &s, &c);
            tw2[w][u] = pk2(c, -s);
        }
        __syncthreads();

        int c = tid & 127, ys = tid >> 7;
        int b = blockIdx.x >> 6;
        int y = ((blockIdx.x & 63) << 1) | ys;
        const float* base = X + ((size_t)(b * NHH + y) * NWW) * CI + c;

        float v0  = base[0],       v32 = base[32 * CI];
        float v64 = base[64 * CI], v96 = base[96 * CI];
        float pE0  = v0 + v64,  pO0  = v0 - v64;
        float pE32 = v32 + v96, pO32 = v32 - v96;

        u64 accE[9], accO[8];
#pragma unroll
        for (int e = 0; e < 9; e++)
            accE[e] = pk2(pE0 + ((e & 1) ? -pE32 : pE32), 0.f);
#pragma unroll
        for (int o = 0; o < 8; o++)
            accO[o] = pk2(pO0, (o & 1) ? pO32 : -pO32);

        for (int u = 1; u < 32; u++) {
            float va = base[u * CI];
            float vb = base[(u + 64) * CI];
            float vc = base[(64 - u) * CI];
            float vd = base[(128 - u) * CI];
            float pEu = va + vb, pOu = va - vb;
            float pEv = vc + vd, pOv = vc - vd;
            u64 sdE = pk2(pEu + pEv, pEu - pEv);
            u64 dsO = pk2(pOu - pOv, pOu + pOv);
#pragma unroll
            for (int e = 0; e < 9; e++)
                accE[e] = f2fma(sdE, tw2[2 * e][u], accE[e]);
#pragma unroll
            for (int o = 0; o < 8; o++)
                accO[o] = f2fma(dsO, tw2[2 * o + 1][u], accO[o]);
        }

        u64* dst = g_X1 + ((size_t)b * WM * NHH + y) * CI + c;
#pragma unroll
        for (int w = 0; w < WM; w++)
            dst[(size_t)w * NHH * CI] = (w & 1) ? accO[w >> 1] : accE[w >> 1];
    } else {
        // ------------------- S build -------------------
        int t0 = blockIdx.x - SFW_FWDW_BLOCKS;
        int bx = t0 % ((HM + WM) * DEG);     // axis/mode/d
        int i0 = (t0 / ((HM + WM) * DEG)) * 16;
        int which = (bx >= HM * DEG);
        int hd = which ? (bx - HM * DEG) : bx;
        const float2* ko = which ? ko1 : ko0;
        const float2* ki = which ? ki1 : ki0;
        float4* S = which ? g_S1 : g_S0;
        int h = hd >> 1;
        int d = hd & 1;
        int j = tid & 127, ih = tid >> 7;

        float2 acc[8];
#pragma unroll
        for (int ii = 0; ii < 8; ii++) acc[ii] = make_float2(0.f, 0.f);

        for (int r0 = 0; r0 < RANK; r0 += 32) {
            __syncthreads();
            for (int t = tid; t < 128 * 32; t += 256) {
                int jj = t >> 5, r = t & 31;
                kis[jj][r] = ki[((h * CI + jj) * DEG + d) * RANK + r0 + r];
            }
            for (int t = tid; t < 16 * 32; t += 256) {
                int ii = t >> 5, r = t & 31;
                kos[ii][r] = ko[((h * CO + i0 + ii) * DEG + d) * RANK + r0 + r];
            }
            __syncthreads();
            for (int r = 0; r < 32; r++) {
                float2 bj = kis[j][r];
#pragma unroll
                for (int ii = 0; ii < 8; ii++)
                    acc[ii] = cfma(kos[ih * 8 + ii][r], bj, acc[ii]);
            }
        }
#pragma unroll
        for (int ii = 0; ii < 8; ii++) {
            int i = i0 + ih * 8 + ii;
            ((float2*)&S[(size_t)(h * CO + i) * CI + j])[d] = acc[ii];
        }
    }
}

// ---------------------------------------------------------------------------
// Forward H DFT (32 kept modes), even/odd + pair fold, f32x2.
// ---------------------------------------------------------------------------
__global__ void __launch_bounds__(1024) fwdH_kernel() {
    __shared__ u64 stg[4][16][128];
    __shared__ u64 twcc[128], twss[128];
    int tid = threadIdx.x;
    if (tid < 128) {
        float s, c;
        sincospif((float)tid / 64.0f, &s, &c);
        twcc[tid] = pk2(c, c);
        twss[tid] = pk2(s, s);
    }
    int b = blockIdx.x / WM, w = blockIdx.x % WM;
    int lane = tid & 31, h = tid >> 5;
    int m = (h < 16) ? h : (96 + h);
    int p = h & 1;
    float sg = ((h >> 1) & 1) ? -1.f : 1.f;
    const u64* src = g_X1 + ((size_t)b * WM + w) * NHH * CI;

    u64 acc[4];
#pragma unroll
    for (int q = 0; q < 4; q++) {
        int c = lane + 32 * q;
        float r0, i0, r32, i32, r64, i64, r96, i96;
        up2(src[c], r0, i0);
        up2(src[32 * CI + c], r32, i32);
        up2(src[64 * CI + c], r64, i64);
        up2(src[96 * CI + c], r96, i96);
        if (p == 0) {
            acc[q] = pk2(fmaf(sg, r32 + r96, r0 + r64),
                         fmaf(sg, i32 + i96, i0 + i64));
        } else {
            acc[q] = pk2(fmaf(sg, i32 - i96, r0 - r64),
                         fmaf(-sg, r32 - r96, i0 - i64));
        }
    }

    const u64* sPtr = p ? &stg[2][0][0] : &stg[0][0][0];
    const u64* mPtr = p ? &stg[3][0][0] : &stg[1][0][0];

    for (int chunk = 0; chunk < 2; chunk++) {
        int ylo = 1 + 16 * chunk;
        int cnt = chunk ? 15 : 16;
        __syncthreads();
        for (int t = tid; t < cnt * 128; t += 1024) {
            int yy = t >> 7, cc = t & 127;
            int yp = ylo + yy;
            float ar, ai, br, bi, cr, ci2, dr, di;
            up2(src[(size_t)yp * CI + cc], ar, ai);
            up2(src[(size_t)(yp + 64) * CI + cc], br, bi);
            up2(src[(size_t)(64 - yp) * CI + cc], cr, ci2);
            up2(src[(size_t)(128 - yp) * CI + cc], dr, di);
            float pEyr = ar + br, pEyi = ai + bi;
            float pOyr = ar - br, pOyi = ai - bi;
            float pEvr = cr + dr, pEvi = ci2 + di;
            float pOvr = cr - dr, pOvi = ci2 - di;
            stg[0][yy][cc] = pk2(pEyr + pEvr, pEyi + pEvi);
            stg[1][yy][cc] = pk2(pEyi - pEvi, -(pEyr - pEvr));
            stg[2][yy][cc] = pk2(pOyr - pOvr, pOyi - pOvi);
            stg[3][yy][cc] = pk2(pOyi + pOvi, -(pOyr + pOvr));
        }
        __syncthreads();
#pragma unroll 4
        for (int yy = 0; yy < cnt; yy++) {
            int idx = (m * (ylo + yy)) & 127;
            u64 cc = twcc[idx], ss = twss[idx];
#pragma unroll
            for (int q = 0; q < 4; q++) {
                int c = lane + 32 * q;
                acc[q] = f2fma(sPtr[yy * 128 + c], cc, acc[q]);
                acc[q] = f2fma(mPtr[yy * 128 + c], ss, acc[q]);
            }
        }
    }
    u64* dst = (u64*)g_Xf + ((size_t)(h * WM + w) * BATCH + b) * CI;
#pragma unroll
    for (int q = 0; q < 4; q++) dst[lane + 32 * q] = acc[q];
}

// ---------------------------------------------------------------------------
// Mode mix (measured-best 87.5us version, unchanged).
// ---------------------------------------------------------------------------
__global__ void __launch_bounds__(512, 2) mix_kernel() {
    __shared__ ulonglong2 xsm[32][64];
    __shared__ float4 Ksm[4][129];
    int tid = threadIdx.x;
    int hw = blockIdx.x;
    int h = hw / WM, w = hw % WM;
    int i = tid & 127, bq = tid >> 7;
    const float4* A  = g_S0 + (size_t)h * CO * CI;
    const float4* Bm = g_S1 + (size_t)w * CO * CI;
    const u64* Xb = (const u64*)g_Xf + (size_t)hw * BATCH * CI;
    const float SCALE = 1.0f / 16384.0f;

    u64* xflat = (u64*)xsm;
    for (int t = tid; t < 32 * 128; t += 512)
        xflat[t] = Xb[(t >> 7) * CI + (t & 127)];

    int kjj2 = tid & 3, kii = tid >> 2;

    u64 accP[8], accQ[8];
#pragma unroll
    for (int bb = 0; bb < 8; bb++) { accP[bb] = 0; accQ[bb] = 0; }

    for (int chunk = 0; chunk < 16; chunk++) {
        __syncthreads();
        {
            int e = kii * CI + chunk * 8 + 2 * kjj2;
            float4 pa0 = A[e], pa1 = A[e + 1];
            float4 pb0 = Bm[e], pb1 = Bm[e + 1];
            float kr0 = pa0.x * pb0.x - pa0.y * pb0.y + pa0.z * pb0.z - pa0.w * pb0.w;
            float ki0 = pa0.x * pb0.y + pa0.y * pb0.x + pa0.z * pb0.w + pa0.w * pb0.z;
            float kr1 = pa1.x * pb1.x - pa1.y * pb1.y + pa1.z * pb1.z - pa1.w * pb1.w;
            float ki1 = pa1.x * pb1.y + pa1.y * pb1.x + pa1.z * pb1.w + pa1.w * pb1.z;
            Ksm[kjj2][kii] = make_float4(kr0 * SCALE, ki0 * SCALE, kr1 * SCALE, ki1 * SCALE);
        }
        __syncthreads();
#pragma unroll
        for (int jj2 = 0; jj2 < 4; jj2++) {
            float4 kk = Ksm[jj2][i];
            u64 kc0 = pk2(kk.x, kk.x), ks0 = pk2(kk.y, kk.y);
            u64 kc1 = pk2(kk.z, kk.z), ks1 = pk2(kk.w, kk.w);
            int jidx = chunk * 4 + jj2;
#pragma unroll
            for (int bb = 0; bb < 8; bb++) {
                ulonglong2 xx = xsm[bq * 8 + bb][jidx];
                accP[bb] = f2fma(xx.x, kc0, accP[bb]);
                accQ[bb] = f2fma(xx.x, ks0, accQ[bb]);
                accP[bb] = f2fma(xx.y, kc1, accP[bb]);
                accQ[bb] = f2fma(xx.y, ks1, accQ[bb]);
            }
        }
    }
    float2* dst = g_Yf + (size_t)hw * BATCH * CO;
#pragma unroll
    for (int bb = 0; bb < 8; bb++) {
        float pr, pi, qr, qi;
        up2(accP[bb], pr, pi);
        up2(accQ[bb], qr, qi);
        dst[(bq * 8 + bb) * CO + i] = make_float2(pr - qi, pi + qr);
    }
}

// ---------------------------------------------------------------------------
// Inverse H with even/odd output split: Z(y)=accE+accO, Z(y+64)=accE-accO.
// ---------------------------------------------------------------------------
__global__ void __launch_bounds__(512) invH_kernel() {
    __shared__ u64 ys[32][128];
    __shared__ u64 twcc[128];
    __shared__ u64 twss[128];
    int tid = threadIdx.x;
    if (tid < 128) {
        float s, c;
        sincospif((float)tid / 64.0f, &s, &c);
        twcc[tid] = pk2(c, c);
        twss[tid] = pk2(s, s);
    }
    int hw = blockIdx.x;
    int b = hw / WM, w = hw % WM;
    int i = tid & 127, ysub = tid >> 7;
    int yb = blockIdx.y * 32 + ysub * 8;   // y in [0,64)

    const u64* Ysrc = (const u64*)g_Yf;
    for (int t = tid; t < 32 * 128; t += 512) {
        int h = t >> 7, ii = t & 127;
        ys[h][ii] = Ysrc[((size_t)(h * WM + w) * BATCH + b) * CO + ii];
    }
    __syncthreads();

    u64 accE[8], accO[8];
    {
        u64 v0 = ys[0][i];
#pragma unroll
        for (int k = 0; k < 8; k++) { accE[k] = v0; accO[k] = 0; }
    }
    {   // m = -16 (h=16, even)
        u64 v = ys[16][i];
        float vr, vi; up2(v, vr, vi);
        u64 vs = pk2(vi, -vr);
        int idx = (16 * yb) & 127;
#pragma unroll
        for (int k = 0; k < 8; k++) {
            accE[k] = f2fma(v,  twcc[idx], accE[k]);
            accE[k] = f2fma(vs, twss[idx], accE[k]);
            idx = (idx + 16) & 127;
        }
    }
#pragma unroll 2
    for (int m = 2; m < 16; m += 2) {
        u64 y1 = ys[m][i], y2 = ys[32 - m][i];
        float ar, ai, br, bi;
        up2(y1, ar, ai); up2(y2, br, bi);
        u64 s  = pk2(ar + br, ai + bi);
        u64 dp = pk2(-(ai - bi), ar - br);
        int idx = (m * yb) & 127;
#pragma unroll
        for (int k = 0; k < 8; k++) {
            accE[k] = f2fma(s,  twcc[idx], accE[k]);
            accE[k] = f2fma(dp, twss[idx], accE[k]);
            idx = (idx + m) & 127;
        }
    }
#pragma unroll 2
    for (int m = 1; m < 16; m += 2) {
        u64 y1 = ys[m][i], y2 = ys[32 - m][i];
        float ar, ai, br, bi;
        up2(y1, ar, ai); up2(y2, br, bi);
        u64 s  = pk2(ar + br, ai + bi);
        u64 dp = pk2(-(ai - bi), ar - br);
        int idx = (m * yb) & 127;
#pragma unroll
        for (int k = 0; k < 8; k++) {
            accO[k] = f2fma(s,  twcc[idx], accO[k]);
            accO[k] = f2fma(dp, twss[idx], accO[k]);
            idx = (idx + m) & 127;
        }
    }
    u64* Zd = (u64*)g_Z;
    const u64 NEG1 = pk2(-1.f, -1.f);
#pragma unroll
    for (int k = 0; k < 8; k++) {
        int y = yb + k;
        Zd[((size_t)(b * NHH + y) * WM + w) * CO + i] = f2add(accE[k], accO[k]);
        Zd[((size_t)(b * NHH + y + 64) * WM + w) * CO + i] = f2fma(accO[k], NEG1, accE[k]);
    }
}

// ---------------------------------------------------------------------------
// Inverse W (hermitian, real output), even/odd + pair symmetry, f32x2,
// split accumulator chains. 256 threads = 2 y rows.
// ---------------------------------------------------------------------------
__global__ void __launch_bounds__(256) invW_kernel(float* __restrict__ out) {
    __shared__ u64 tw2[17][33];
    int tid = threadIdx.x;
    for (int t = tid; t < 17 * 33; t += 256) {
        int w = t / 33, x = t % 33;
        float s, c;
        sincospif((float)(w * x) / 64.0f, &s, &c);
        tw2[w][x] = pk2(c, -s);
    }
    __syncthreads();

    int c = tid & 127, ysp = tid >> 7;
    int b = blockIdx.x >> 6;
    int y = ((blockIdx.x & 63) << 1) | ysp;
    const float2* zrow = g_Z + (size_t)(b * NHH + y) * WM * CO;

    u64 zw[WM];
#pragma unroll
    for (int w = 0; w < WM; w++) {
        float2 v = zrow[w * CO + c];
        float cw = (w == 0) ? 1.0f : 2.0f;
        zw[w] = pk2(v.x * cw, v.y * cw);
    }

    float* orow = out + (size_t)(b * NHH + y) * NWW * CO + c;
    for (int x = 0; x <= 32; x++) {
        u64 aE0 = 0, aE1 = 0, aO0 = 0, aO1 = 0;
#pragma unroll
        for (int e = 0; e < 5; e++)
            aE0 = f2fma(zw[2 * e], tw2[2 * e][x], aE0);
#pragma unroll
        for (int e = 5; e < 9; e++)
            aE1 = f2fma(zw[2 * e], tw2[2 * e][x], aE1);
#pragma unroll
        for (int o = 0; o < 4; o++)
            aO0 = f2fma(zw[2 * o + 1], tw2[2 * o + 1][x], aO0);
#pragma unroll
        for (int o = 4; o < 8; o++)
            aO1 = f2fma(zw[2 * o + 1], tw2[2 * o + 1][x], aO1);
        u64 aE = f2add(aE0, aE1);
        u64 aO = f2add(aO0, aO1);
        float eR, eI, oR, oI;
        up2(aE, eR, eI);
        up2(aO, oR, oI);
        float a0 = eR + oR, b0 = eI + oI;
        float a1 = eR - oR, b1 = eI - oI;
        if (x == 0) {
            orow[0]            = a0 + b0;
            orow[64 * CO]      = a1 + b1;
        } else if (x == 32) {
            orow[32 * CO]      = a0 + b0;
            orow[96 * CO]      = a1 + b1;
        } else {
            orow[(size_t)x * CO]          = a0 + b0;
            orow[(size_t)(128 - x) * CO]  = a0 - b0;
            orow[(size_t)(x + 64) * CO]   = a1 + b1;
            orow[(size_t)(64 - x) * CO]   = a1 - b1;
        }
    }
}

// ---------------------------------------------------------------------------
extern "C" void kernel_launch(void* const* d_in, const int* in_sizes, int n_in,
                              void* d_out, int out_size) {
    const float*  X   = (const float*) d_in[0];
    const float2* ko0 = (const float2*)d_in[1];
    const float2* ki0 = (const float2*)d_in[2];
    const float2* ko1 = (const float2*)d_in[3];
    const float2* ki1 = (const float2*)d_in[4];
    float* out = (float*)d_out;

    s_fwdW_kernel<<<SFW_TOTAL, 256>>>(X, ko0, ki0, ko1, ki1);
    fwdH_kernel<<<BATCH * WM, 1024>>>();
    mix_kernel<<<NHW, 512>>>();
    invH_kernel<<<dim3(BATCH * WM, 2), 512>>>();
    invW_kernel<<<BATCH * 64, 256>>>(out);
}

// round 16
// speedup vs baseline: 1.0864x; 1.0179x over previous
#include <cuda_runtime.h>
#include <math.h>

// ---------------------------------------------------------------------------
// TensorizedSpectralConv: B=32, H=W=128, C=128, modes 32x17, deg 2, rank 64
// Round 15: invH 256-entry twiddle tables + fully unrolled m-loops (index ALU
// eliminated -> LDS immediate offsets); invW branch-peeled x loop.
// Base = 337.9us config (s merged into fwdW launch).
// ---------------------------------------------------------------------------

#define BATCH 32
#define NHH   128
#define NWW   128
#define CI    128
#define CO    128
#define WM    17
#define HM    32
#define DEG   2
#define RANK  64
#define NHW   (HM*WM)   // 544

typedef unsigned long long u64;

__device__ u64    g_X1[BATCH*WM*NHH*CI];     // 71.3 MB  [b][w][y][c] (re,im)
__device__ float4 g_S0[HM*CO*CI];            //  8.4 MB
__device__ float4 g_S1[WM*CO*CI];            //  4.5 MB
__device__ float2 g_Xf[NHW*BATCH*CI];        // 17.8 MB  [h][w][b][c]
__device__ float2 g_Yf[NHW*BATCH*CO];        // 17.8 MB  [h][w][b][i]
__device__ float2 g_Z [BATCH*NHH*WM*CO];     // 71.3 MB  [b][y][w][i]

__device__ __forceinline__ u64 pk2(float x, float y) {
    u64 r; asm("mov.b64 %0,{%1,%2};" : "=l"(r) : "f"(x), "f"(y)); return r;
}
__device__ __forceinline__ void up2(u64 v, float& x, float& y) {
    asm("mov.b64 {%0,%1},%2;" : "=f"(x), "=f"(y) : "l"(v));
}
__device__ __forceinline__ u64 f2fma(u64 a, u64 b, u64 c) {
    u64 d; asm("fma.rn.f32x2 %0,%1,%2,%3;" : "=l"(d) : "l"(a), "l"(b), "l"(c)); return d;
}
__device__ __forceinline__ u64 f2add(u64 a, u64 b) {
    u64 d; asm("add.rn.f32x2 %0,%1,%2;" : "=l"(d) : "l"(a), "l"(b)); return d;
}

__device__ __forceinline__ float2 cfma(float2 a, float2 b, float2 acc) {
    acc.x = fmaf(a.x, b.x, acc.x);
    acc.x = fmaf(-a.y, b.y, acc.x);
    acc.y = fmaf(a.x, b.y, acc.y);
    acc.y = fmaf(a.y, b.x, acc.y);
    return acc;
}

// ---------------------------------------------------------------------------
// Merged launch: blocks [0, 2048) = fwdW; blocks [2048, 2832) = S build.
// ---------------------------------------------------------------------------
#define SFW_FWDW_BLOCKS (BATCH * 64)            // 2048
#define SFW_S_BLOCKS    ((HM + WM) * DEG * 8)   // 784
#define SFW_TOTAL       (SFW_FWDW_BLOCKS + SFW_S_BLOCKS)

__global__ void __launch_bounds__(256) s_fwdW_kernel(
    const float* __restrict__ X,
    const float2* __restrict__ ko0, const float2* __restrict__ ki0,
    const float2* __restrict__ ko1, const float2* __restrict__ ki1) {
    __shared__ u64 tw2[17][33];
    __shared__ float2 kis[128][33];
    __shared__ float2 kos[16][33];
    int tid = threadIdx.x;

    if (blockIdx.x < SFW_FWDW_BLOCKS) {
        // ------------------- fwdW -------------------
        for (int t = tid; t < 17 * 33; t += 256) {
            int w = t / 33, u = t % 33;
            float s, c;
            sincospif((float)(w * u) / 64.0f, &s, &c);
            tw2[w][u] = pk2(c, -s);
        }
        __syncthreads();

        int c = tid & 127, ys = tid >> 7;
        int b = blockIdx.x >> 6;
        int y = ((blockIdx.x & 63) << 1) | ys;
        const float* base = X + ((size_t)(b * NHH + y) * NWW) * CI + c;

        float v0  = base[0],       v32 = base[32 * CI];
        float v64 = base[64 * CI], v96 = base[96 * CI];
        float pE0  = v0 + v64,  pO0  = v0 - v64;
        float pE32 = v32 + v96, pO32 = v32 - v96;

        u64 accE[9], accO[8];
#pragma unroll
        for (int e = 0; e < 9; e++)
            accE[e] = pk2(pE0 + ((e & 1) ? -pE32 : pE32), 0.f);
#pragma unroll
        for (int o = 0; o < 8; o++)
            accO[o] = pk2(pO0, (o & 1) ? pO32 : -pO32);

        for (int u = 1; u < 32; u++) {
            float va = base[u * CI];
            float vb = base[(u + 64) * CI];
            float vc = base[(64 - u) * CI];
            float vd = base[(128 - u) * CI];
            float pEu = va + vb, pOu = va - vb;
            float pEv = vc + vd, pOv = vc - vd;
            u64 sdE = pk2(pEu + pEv, pEu - pEv);
            u64 dsO = pk2(pOu - pOv, pOu + pOv);
#pragma unroll
            for (int e = 0; e < 9; e++)
                accE[e] = f2fma(sdE, tw2[2 * e][u], accE[e]);
#pragma unroll
            for (int o = 0; o < 8; o++)
                accO[o] = f2fma(dsO, tw2[2 * o + 1][u], accO[o]);
        }

        u64* dst = g_X1 + ((size_t)b * WM * NHH + y) * CI + c;
#pragma unroll
        for (int w = 0; w < WM; w++)
            dst[(size_t)w * NHH * CI] = (w & 1) ? accO[w >> 1] : accE[w >> 1];
    } else {
        // ------------------- S build -------------------
        int t0 = blockIdx.x - SFW_FWDW_BLOCKS;
        int bx = t0 % ((HM + WM) * DEG);
        int i0 = (t0 / ((HM + WM) * DEG)) * 16;
        int which = (bx >= HM * DEG);
        int hd = which ? (bx - HM * DEG) : bx;
        const float2* ko = which ? ko1 : ko0;
        const float2* ki = which ? ki1 : ki0;
        float4* S = which ? g_S1 : g_S0;
        int h = hd >> 1;
        int d = hd & 1;
        int j = tid & 127, ih = tid >> 7;

        float2 acc[8];
#pragma unroll
        for (int ii = 0; ii < 8; ii++) acc[ii] = make_float2(0.f, 0.f);

        for (int r0 = 0; r0 < RANK; r0 += 32) {
            __syncthreads();
            for (int t = tid; t < 128 * 32; t += 256) {
                int jj = t >> 5, r = t & 31;
                kis[jj][r] = ki[((h * CI + jj) * DEG + d) * RANK + r0 + r];
            }
            for (int t = tid; t < 16 * 32; t += 256) {
                int ii = t >> 5, r = t & 31;
                kos[ii][r] = ko[((h * CO + i0 + ii) * DEG + d) * RANK + r0 + r];
            }
            __syncthreads();
            for (int r = 0; r < 32; r++) {
                float2 bj = kis[j][r];
#pragma unroll
                for (int ii = 0; ii < 8; ii++)
                    acc[ii] = cfma(kos[ih * 8 + ii][r], bj, acc[ii]);
            }
        }
#pragma unroll
        for (int ii = 0; ii < 8; ii++) {
            int i = i0 + ih * 8 + ii;
            ((float2*)&S[(size_t)(h * CO + i) * CI + j])[d] = acc[ii];
        }
    }
}

// ---------------------------------------------------------------------------
// Forward H DFT (32 kept modes), even/odd + pair fold, f32x2.
// ---------------------------------------------------------------------------
__global__ void __launch_bounds__(1024) fwdH_kernel() {
    __shared__ u64 stg[4][16][128];
    __shared__ u64 twcc[128], twss[128];
    int tid = threadIdx.x;
    if (tid < 128) {
        float s, c;
        sincospif((float)tid / 64.0f, &s, &c);
        twcc[tid] = pk2(c, c);
        twss[tid] = pk2(s, s);
    }
    int b = blockIdx.x / WM, w = blockIdx.x % WM;
    int lane = tid & 31, h = tid >> 5;
    int m = (h < 16) ? h : (96 + h);
    int p = h & 1;
    float sg = ((h >> 1) & 1) ? -1.f : 1.f;
    const u64* src = g_X1 + ((size_t)b * WM + w) * NHH * CI;

    u64 acc[4];
#pragma unroll
    for (int q = 0; q < 4; q++) {
        int c = lane + 32 * q;
        float r0, i0, r32, i32, r64, i64, r96, i96;
        up2(src[c], r0, i0);
        up2(src[32 * CI + c], r32, i32);
        up2(src[64 * CI + c], r64, i64);
        up2(src[96 * CI + c], r96, i96);
        if (p == 0) {
            acc[q] = pk2(fmaf(sg, r32 + r96, r0 + r64),
                         fmaf(sg, i32 + i96, i0 + i64));
        } else {
            acc[q] = pk2(fmaf(sg, i32 - i96, r0 - r64),
                         fmaf(-sg, r32 - r96, i0 - i64));
        }
    }

    const u64* sPtr = p ? &stg[2][0][0] : &stg[0][0][0];
    const u64* mPtr = p ? &stg[3][0][0] : &stg[1][0][0];

    for (int chunk = 0; chunk < 2; chunk++) {
        int ylo = 1 + 16 * chunk;
        int cnt = chunk ? 15 : 16;
        __syncthreads();
        for (int t = tid; t < cnt * 128; t += 1024) {
            int yy = t >> 7, cc = t & 127;
            int yp = ylo + yy;
            float ar, ai, br, bi, cr, ci2, dr, di;
            up2(src[(size_t)yp * CI + cc], ar, ai);
            up2(src[(size_t)(yp + 64) * CI + cc], br, bi);
            up2(src[(size_t)(64 - yp) * CI + cc], cr, ci2);
            up2(src[(size_t)(128 - yp) * CI + cc], dr, di);
            float pEyr = ar + br, pEyi = ai + bi;
            float pOyr = ar - br, pOyi = ai - bi;
            float pEvr = cr + dr, pEvi = ci2 + di;
            float pOvr = cr - dr, pOvi = ci2 - di;
            stg[0][yy][cc] = pk2(pEyr + pEvr, pEyi + pEvi);
            stg[1][yy][cc] = pk2(pEyi - pEvi, -(pEyr - pEvr));
            stg[2][yy][cc] = pk2(pOyr - pOvr, pOyi - pOvi);
            stg[3][yy][cc] = pk2(pOyi + pOvi, -(pOyr + pOvr));
        }
        __syncthreads();
#pragma unroll 4
        for (int yy = 0; yy < cnt; yy++) {
            int idx = (m * (ylo + yy)) & 127;
            u64 cc = twcc[idx], ss = twss[idx];
#pragma unroll
            for (int q = 0; q < 4; q++) {
                int c = lane + 32 * q;
                acc[q] = f2fma(sPtr[yy * 128 + c], cc, acc[q]);
                acc[q] = f2fma(mPtr[yy * 128 + c], ss, acc[q]);
            }
        }
    }
    u64* dst = (u64*)g_Xf + ((size_t)(h * WM + w) * BATCH + b) * CI;
#pragma unroll
    for (int q = 0; q < 4; q++) dst[lane + 32 * q] = acc[q];
}

// ---------------------------------------------------------------------------
// Mode mix (measured-best 87.5us version, unchanged).
// ---------------------------------------------------------------------------
__global__ void __launch_bounds__(512, 2) mix_kernel() {
    __shared__ ulonglong2 xsm[32][64];
    __shared__ float4 Ksm[4][129];
    int tid = threadIdx.x;
    int hw = blockIdx.x;
    int h = hw / WM, w = hw % WM;
    int i = tid & 127, bq = tid >> 7;
    const float4* A  = g_S0 + (size_t)h * CO * CI;
    const float4* Bm = g_S1 + (size_t)w * CO * CI;
    const u64* Xb = (const u64*)g_Xf + (size_t)hw * BATCH * CI;
    const float SCALE = 1.0f / 16384.0f;

    u64* xflat = (u64*)xsm;
    for (int t = tid; t < 32 * 128; t += 512)
        xflat[t] = Xb[(t >> 7) * CI + (t & 127)];

    int kjj2 = tid & 3, kii = tid >> 2;

    u64 accP[8], accQ[8];
#pragma unroll
    for (int bb = 0; bb < 8; bb++) { accP[bb] = 0; accQ[bb] = 0; }

    for (int chunk = 0; chunk < 16; chunk++) {
        __syncthreads();
        {
            int e = kii * CI + chunk * 8 + 2 * kjj2;
            float4 pa0 = A[e], pa1 = A[e + 1];
            float4 pb0 = Bm[e], pb1 = Bm[e + 1];
            float kr0 = pa0.x * pb0.x - pa0.y * pb0.y + pa0.z * pb0.z - pa0.w * pb0.w;
            float ki0 = pa0.x * pb0.y + pa0.y * pb0.x + pa0.z * pb0.w + pa0.w * pb0.z;
            float kr1 = pa1.x * pb1.x - pa1.y * pb1.y + pa1.z * pb1.z - pa1.w * pb1.w;
            float ki1 = pa1.x * pb1.y + pa1.y * pb1.x + pa1.z * pb1.w + pa1.w * pb1.z;
            Ksm[kjj2][kii] = make_float4(kr0 * SCALE, ki0 * SCALE, kr1 * SCALE, ki1 * SCALE);
        }
        __syncthreads();
#pragma unroll
        for (int jj2 = 0; jj2 < 4; jj2++) {
            float4 kk = Ksm[jj2][i];
            u64 kc0 = pk2(kk.x, kk.x), ks0 = pk2(kk.y, kk.y);
            u64 kc1 = pk2(kk.z, kk.z), ks1 = pk2(kk.w, kk.w);
            int jidx = chunk * 4 + jj2;
#pragma unroll
            for (int bb = 0; bb < 8; bb++) {
                ulonglong2 xx = xsm[bq * 8 + bb][jidx];
                accP[bb] = f2fma(xx.x, kc0, accP[bb]);
                accQ[bb] = f2fma(xx.x, ks0, accQ[bb]);
                accP[bb] = f2fma(xx.y, kc1, accP[bb]);
                accQ[bb] = f2fma(xx.y, ks1, accQ[bb]);
            }
        }
    }
    float2* dst = g_Yf + (size_t)hw * BATCH * CO;
#pragma unroll
    for (int bb = 0; bb < 8; bb++) {
        float pr, pi, qr, qi;
        up2(accP[bb], pr, pi);
        up2(accQ[bb], qr, qi);
        dst[(bq * 8 + bb) * CO + i] = make_float2(pr - qi, pi + qr);
    }
}

// ---------------------------------------------------------------------------
// Inverse H, even/odd output split, 256-entry twiddle tables, full unroll:
// twiddle offsets become compile-time constants -> LDS immediate addressing.
// ---------------------------------------------------------------------------
__global__ void __launch_bounds__(512) invH_kernel() {
    __shared__ u64 ys[32][128];
    __shared__ u64 twcc[256];
    __shared__ u64 twss[256];
    int tid = threadIdx.x;
    if (tid < 128) {
        float s, c;
        sincospif((float)tid / 64.0f, &s, &c);
        twcc[tid] = pk2(c, c);
        twss[tid] = pk2(s, s);
        twcc[tid + 128] = pk2(c, c);
        twss[tid + 128] = pk2(s, s);
    }
    int hw = blockIdx.x;
    int b = hw / WM, w = hw % WM;
    int i = tid & 127, ysub = tid >> 7;
    int yb = blockIdx.y * 32 + ysub * 8;   // y in [0,64)

    const u64* Ysrc = (const u64*)g_Yf;
    for (int t = tid; t < 32 * 128; t += 512) {
        int h = t >> 7, ii = t & 127;
        ys[h][ii] = Ysrc[((size_t)(h * WM + w) * BATCH + b) * CO + ii];
    }
    __syncthreads();

    u64 accE[8], accO[8];
    {
        u64 v0 = ys[0][i];
#pragma unroll
        for (int k = 0; k < 8; k++) { accE[k] = v0; accO[k] = 0; }
    }
    {   // m = -16 (h=16, even)
        u64 v = ys[16][i];
        float vr, vi; up2(v, vr, vi);
        u64 vs = pk2(vi, -vr);
        int idx0 = (16 * yb) & 127;
        const u64* tc = twcc + idx0;
        const u64* ts = twss + idx0;
#pragma unroll
        for (int k = 0; k < 8; k++) {
            accE[k] = f2fma(v,  tc[k * 16], accE[k]);
            accE[k] = f2fma(vs, ts[k * 16], accE[k]);
        }
    }
#pragma unroll
    for (int m = 2; m < 16; m += 2) {
        u64 y1 = ys[m][i], y2 = ys[32 - m][i];
        float ar, ai, br, bi;
        up2(y1, ar, ai); up2(y2, br, bi);
        u64 s  = pk2(ar + br, ai + bi);
        u64 dp = pk2(-(ai - bi), ar - br);
        int idx0 = (m * yb) & 127;
        const u64* tc = twcc + idx0;
        const u64* ts = twss + idx0;
#pragma unroll
        for (int k = 0; k < 8; k++) {
            accE[k] = f2fma(s,  tc[k * m], accE[k]);
            accE[k] = f2fma(dp, ts[k * m], accE[k]);
        }
    }
#pragma unroll
    for (int m = 1; m < 16; m += 2) {
        u64 y1 = ys[m][i], y2 = ys[32 - m][i];
        float ar, ai, br, bi;
        up2(y1, ar, ai); up2(y2, br, bi);
        u64 s  = pk2(ar + br, ai + bi);
        u64 dp = pk2(-(ai - bi), ar - br);
        int idx0 = (m * yb) & 127;
        const u64* tc = twcc + idx0;
        const u64* ts = twss + idx0;
#pragma unroll
        for (int k = 0; k < 8; k++) {
            accO[k] = f2fma(s,  tc[k * m], accO[k]);
            accO[k] = f2fma(dp, ts[k * m], accO[k]);
        }
    }
    u64* Zd = (u64*)g_Z;
    const u64 NEG1 = pk2(-1.f, -1.f);
#pragma unroll
    for (int k = 0; k < 8; k++) {
        int y = yb + k;
        Zd[((size_t)(b * NHH + y) * WM + w) * CO + i] = f2add(accE[k], accO[k]);
        Zd[((size_t)(b * NHH + y + 64) * WM + w) * CO + i] = f2fma(accO[k], NEG1, accE[k]);
    }
}

// ---------------------------------------------------------------------------
// Inverse W (hermitian, real output), even/odd + pair symmetry, f32x2,
// split accumulator chains, x=0/32 peeled (branch-free main loop).
// ---------------------------------------------------------------------------
__global__ void __launch_bounds__(256) invW_kernel(float* __restrict__ out) {
    __shared__ u64 tw2[17][33];
    int tid = threadIdx.x;
    for (int t = tid; t < 17 * 33; t += 256) {
        int w = t / 33, x = t % 33;
        float s, c;
        sincospif((float)(w * x) / 64.0f, &s, &c);
        tw2[w][x] = pk2(c, -s);
    }
    __syncthreads();

    int c = tid & 127, ysp = tid >> 7;
    int b = blockIdx.x >> 6;
    int y = ((blockIdx.x & 63) << 1) | ysp;
    const float2* zrow = g_Z + (size_t)(b * NHH + y) * WM * CO;

    u64 zw[WM];
#pragma unroll
    for (int w = 0; w < WM; w++) {
        float2 v = zrow[w * CO + c];
        float cw = (w == 0) ? 1.0f : 2.0f;
        zw[w] = pk2(v.x * cw, v.y * cw);
    }

    float* orow = out + (size_t)(b * NHH + y) * NWW * CO + c;

    // peel x = 0: tw = (1, 0) for all w -> acc = (sum re, 0); and x = 32.
    {
        float eR = 0.f, oR = 0.f;
#pragma unroll
        for (int e = 0; e < 9; e++) { float r, im; up2(zw[2 * e], r, im); eR += r; }
#pragma unroll
        for (int o = 0; o < 8; o++) { float r, im; up2(zw[2 * o + 1], r, im); oR += r; }
        orow[0]       = eR + oR;
        orow[64 * CO] = eR - oR;
    }
    {
        u64 aE = 0, aO = 0;
#pragma unroll
        for (int e = 0; e < 9; e++)
            aE = f2fma(zw[2 * e], tw2[2 * e][32], aE);
#pragma unroll
        for (int o = 0; o < 8; o++)
            aO = f2fma(zw[2 * o + 1], tw2[2 * o + 1][32], aO);
        float eR, eI, oR, oI;
        up2(aE, eR, eI);
        up2(aO, oR, oI);
        orow[32 * CO] = (eR + oR) + (eI + oI);
        orow[96 * CO] = (eR - oR) + (eI - oI);
    }

    for (int x = 1; x < 32; x++) {
        u64 aE0 = 0, aE1 = 0, aO0 = 0, aO1 = 0;
#pragma unroll
        for (int e = 0; e < 5; e++)
            aE0 = f2fma(zw[2 * e], tw2[2 * e][x], aE0);
#pragma unroll
        for (int e = 5; e < 9; e++)
            aE1 = f2fma(zw[2 * e], tw2[2 * e][x], aE1);
#pragma unroll
        for (int o = 0; o < 4; o++)
            aO0 = f2fma(zw[2 * o + 1], tw2[2 * o + 1][x], aO0);
#pragma unroll
        for (int o = 4; o < 8; o++)
            aO1 = f2fma(zw[2 * o + 1], tw2[2 * o + 1][x], aO1);
        u64 aE = f2add(aE0, aE1);
        u64 aO = f2add(aO0, aO1);
        float eR, eI, oR, oI;
        up2(aE, eR, eI);
        up2(aO, oR, oI);
        float a0 = eR + oR, b0 = eI + oI;   // acc(x)
        float a1 = eR - oR, b1 = eI - oI;   // acc(x+64)
        orow[(size_t)x * CO]         = a0 + b0;
        orow[(size_t)(128 - x) * CO] = a0 - b0;
        orow[(size_t)(x + 64) * CO]  = a1 + b1;
        orow[(size_t)(64 - x) * CO]  = a1 - b1;
    }
}

// ---------------------------------------------------------------------------
extern "C" void kernel_launch(void* const* d_in, const int* in_sizes, int n_in,
                              void* d_out, int out_size) {
    const float*  X   = (const float*) d_in[0];
    const float2* ko0 = (const float2*)d_in[1];
    const float2* ki0 = (const float2*)d_in[2];
    const float2* ko1 = (const float2*)d_in[3];
    const float2* ki1 = (const float2*)d_in[4];
    float* out = (float*)d_out;

    s_fwdW_kernel<<<SFW_TOTAL, 256>>>(X, ko0, ki0, ko1, ki1);
    fwdH_kernel<<<BATCH * WM, 1024>>>();
    mix_kernel<<<NHW, 512>>>();
    invH_kernel<<<dim3(BATCH * WM, 2), 512>>>();
    invW_kernel<<<BATCH * 64, 256>>>(out);
}